// round 15
// baseline (speedup 1.0000x reference)
#include <cuda_runtime.h>
#include <cuda_bf16.h>
#include <math.h>
#include <cstdint>

#define BATCH 2
#define CIN   128
#define TT    5
#define TC    4
#define HH    48
#define WW    48
#define HW    2304
#define HCH   64

// Scratch (device globals -- no allocation allowed)
__device__ float g_y[BATCH*HW*HCH];   // flat [b][p*64+j]

__device__ __forceinline__ uint32_t f22bf(float a, float b) {
    __nv_bfloat162 t = __floats2bfloat162_rn(a, b);
    return *(uint32_t*)&t;
}

// ---------------------------------------------------------------------------
// Fused kernel: projections (HMMA) + attention.
// grid (6,12,2), block 1024 (32 warps = 4x8 pixel tile), 1 CTA/SM.
//
// Smem layout (bytes):
//   [0, 72192)            sgm16: g halos bf16 [t][64 ch][141 pos]
//   [72192, 124416)       W_sm u32 [192 m][68]: rows 0-63 w_phi, 64-127 w_g,
//                         128-191 w_theta (bf16 k-pairs)
//   [124416, 169472)      XU union (45056 B):
//                           xq u32[64][40] -> qbuf f32[32][68]
//                           xstage u32[64][168] -> phiF bf16[140][72]
//                           offT u16[12544] (packed 4-per-u64)
//   [169472, 195072)      satt f32 [32][200] (scores; later bf16 weights)
//   [195072, 195632)      sgp int[140] (clamped halo pixel index)
// ---------------------------------------------------------------------------
#define WS_B    72192
#define XU_B    124416
#define SATT_B  169472
#define SGP_B   195072
#define SMEM_TOT 195632
#define WST 68
#define XST 168

#define MMA_BF16(ACC, A0, A1, A2, A3, B0, B1)                                 \
    asm volatile(                                                             \
        "mma.sync.aligned.m16n8k16.row.col.f32.bf16.bf16.f32 "                \
        "{%0,%1,%2,%3}, {%4,%5,%6,%7}, {%8,%9}, {%0,%1,%2,%3};\n"             \
        : "+f"((ACC)[0]), "+f"((ACC)[1]), "+f"((ACC)[2]), "+f"((ACC)[3])      \
        : "r"(A0), "r"(A1), "r"(A2), "r"(A3), "r"(B0), "r"(B1))

__global__ void __launch_bounds__(1024, 1)
fused_attn_kernel(const float* __restrict__ x,
                  const float* __restrict__ w_theta,
                  const float* __restrict__ w_phi,
                  const float* __restrict__ w_g)
{
    extern __shared__ char smc[];
    __nv_bfloat16* sgm16 = (__nv_bfloat16*)(smc);
    uint32_t*      smW   = (uint32_t*)(smc + WS_B);
    float*         satt  = (float*)(smc + SATT_B);
    __nv_bfloat16* satt16= (__nv_bfloat16*)(smc + SATT_B);
    int*           sgp   = (int*)(smc + SGP_B);

    const int b    = blockIdx.z;
    const int tid  = threadIdx.x;
    const int lane = tid & 31, warp = tid >> 5;
    const int l4 = lane >> 2, lm4 = lane & 3;
    const int ly = warp >> 3, lx = warp & 7;
    const int py = blockIdx.y*4 + ly;
    const int px = blockIdx.x*8 + lx;
    const int p  = py*WW + px;
    const int warpPos = ly*14 + lx;

    // ---- halo pixel table ----
    if (tid < 140) {
        int hy = tid / 14, hx = tid - hy*14;
        int gy = min(max((int)blockIdx.y*4 + hy - 3, 0), HH-1);
        int gx = min(max((int)blockIdx.x*8 + hx - 3, 0), WW-1);
        sgp[tid] = gy*WW + gx;
    }

    // ---- stage stacked weights [phi; g; theta] as bf16 k-pairs ----
    for (int i = tid; i < 192*64; i += 1024) {
        int m = i >> 6, k2 = i & 63;
        const float* row = (m < 64)  ? (w_phi   + m*CIN)
                         : (m < 128) ? (w_g     + (m - 64)*CIN)
                                     : (w_theta + (m - 128)*CIN);
        float2 wv = *(const float2*)(row + 2*k2);
        smW[m*WST + k2] = f22bf(wv.x, wv.y);
    }

    // ---- stage xq: x frame 0 at the 32 tile pixels ----
    {
        uint32_t* xq = (uint32_t*)(smc + XU_B);
        for (int i = tid; i < 2048; i += 1024) {
            int k2 = i >> 5, n = i & 31;
            int pp = (blockIdx.y*4 + (n >> 3))*WW + blockIdx.x*8 + (n & 7);
            const float* xb = x + ((size_t)(b*CIN + 2*k2)*TT)*HW + pp;
            xq[k2*40 + n] = f22bf(xb[0], xb[(size_t)TT*HW]);
        }
    }
    __syncthreads();

    // ---- q MMA: M=64 (theta rows 128-191) x N=32 px, warps 0-7 ----
    if (warp < 8) {
        const uint32_t* xq = (const uint32_t*)(smc + XU_B);
        const int mg = warp & 3, ng = warp >> 2;
        float qa[2][4] = {};
        #pragma unroll
        for (int k8 = 0; k8 < 8; k8++) {
            int r0 = 128 + mg*16 + l4;
            int cA = k8*8 + lm4;
            uint32_t a0 = smW[r0*WST + cA];
            uint32_t a1 = smW[(r0 + 8)*WST + cA];
            uint32_t a2 = smW[r0*WST + cA + 4];
            uint32_t a3 = smW[(r0 + 8)*WST + cA + 4];
            #pragma unroll
            for (int ni = 0; ni < 2; ni++) {
                int n = ng*16 + ni*8 + l4;
                uint32_t b0 = xq[(k8*8 + lm4)*40 + n];
                uint32_t b1 = xq[(k8*8 + lm4 + 4)*40 + n];
                MMA_BF16(qa[ni], a0, a1, a2, a3, b0, b1);
            }
        }
        __syncthreads();                       // xq reads done
        float* qbuf = (float*)(smc + XU_B);    // aliases xq
        #pragma unroll
        for (int ni = 0; ni < 2; ni++) {
            int s = ng*16 + ni*8 + lm4*2;
            int r = mg*16 + l4;
            qbuf[s*68 + r]           = qa[ni][0];
            qbuf[(s + 1)*68 + r]     = qa[ni][1];
            qbuf[s*68 + r + 8]       = qa[ni][2];
            qbuf[(s + 1)*68 + r + 8] = qa[ni][3];
        }
    } else {
        __syncthreads();
    }
    __syncthreads();                           // qbuf ready

    // ---- each warp loads its pixel's q (channel chunk c*8..c*8+7) ----
    const int c   = lane & 7;                  // channel octet
    const int sub = lane >> 3;                 // key within group of 4
    const float* qbuf = (const float*)(smc + XU_B);
    float4 qA = *(const float4*)(qbuf + warp*68 + c*8);
    float4 qB = *(const float4*)(qbuf + warp*68 + c*8 + 4);

    // ---- prefetch frame 0 (f=1) x-halo into registers ----
    uint32_t pre[9];
    #pragma unroll
    for (int j = 0; j < 9; j++) {
        int i = tid + j*1024;
        if (i < 8960) {
            int k2 = i / 140, pos = i - k2*140;
            const float* xb = x + ((size_t)(b*CIN + 2*k2)*TT + 1)*HW;
            int po = sgp[pos];
            pre[j] = f22bf(xb[po], xb[(size_t)TT*HW + po]);
        }
    }

    // ---- frame loop: project phi+g for frame, then score pass ----
    for (int t = 0; t < TC; t++) {
        __syncthreads();                       // prior XU readers done
        uint32_t* xstage = (uint32_t*)(smc + XU_B);
        #pragma unroll
        for (int j = 0; j < 9; j++) {
            int i = tid + j*1024;
            if (i < 8960) {
                int k2 = i / 140, pos = i - k2*140;
                xstage[k2*XST + pos] = pre[j];
            }
        }
        __syncthreads();

        // prefetch next frame while MMA runs
        if (t < 3) {
            const int fn = t + 2;
            #pragma unroll
            for (int j = 0; j < 9; j++) {
                int i = tid + j*1024;
                if (i < 8960) {
                    int k2 = i / 140, pos = i - k2*140;
                    const float* xb = x + ((size_t)(b*CIN + 2*k2)*TT + fn)*HW;
                    int po = sgp[pos];
                    pre[j] = f22bf(xb[po], xb[(size_t)TT*HW + po]);
                }
            }
        }

        // MMA: M=128 (phi 0-63, g 64-127) x N=160 (140 used), all 32 warps
        const int mg = warp & 7, ng = warp >> 3;
        float acc[5][4] = {};
        #pragma unroll
        for (int k8 = 0; k8 < 8; k8++) {
            int r0 = mg*16 + l4;
            int cA = k8*8 + lm4;
            uint32_t a0 = smW[r0*WST + cA];
            uint32_t a1 = smW[(r0 + 8)*WST + cA];
            uint32_t a2 = smW[r0*WST + cA + 4];
            uint32_t a3 = smW[(r0 + 8)*WST + cA + 4];
            #pragma unroll
            for (int ni = 0; ni < 5; ni++) {
                int n = ng*40 + ni*8 + l4;
                uint32_t b0 = xstage[(k8*8 + lm4)*XST + n];
                uint32_t b1 = xstage[(k8*8 + lm4 + 4)*XST + n];
                MMA_BF16(acc[ni], a0, a1, a2, a3, b0, b1);
            }
        }
        __syncthreads();                       // xstage reads done

        // epilogue: phi -> phiF (aliases xstage), g -> sgm16[t]
        __nv_bfloat16* ph16 = (__nv_bfloat16*)(smc + XU_B);
        if (mg < 4) {
            int r = mg*16 + l4;
            #pragma unroll
            for (int ni = 0; ni < 5; ni++) {
                int s = ng*40 + ni*8 + lm4*2;
                if (s < 140) {
                    ph16[s*72 + r]     = __float2bfloat16(acc[ni][0]);
                    ph16[s*72 + r + 8] = __float2bfloat16(acc[ni][2]);
                }
                if (s + 1 < 140) {
                    ph16[(s + 1)*72 + r]     = __float2bfloat16(acc[ni][1]);
                    ph16[(s + 1)*72 + r + 8] = __float2bfloat16(acc[ni][3]);
                }
            }
        } else {
            int h = (mg - 4)*16 + l4;
            #pragma unroll
            for (int ni = 0; ni < 5; ni++) {
                int s = ng*40 + ni*8 + lm4*2;
                if (s < 140) {
                    sgm16[(t*64 + h)*141 + s]     = __float2bfloat16(acc[ni][0]);
                    sgm16[(t*64 + h + 8)*141 + s] = __float2bfloat16(acc[ni][2]);
                }
                if (s + 1 < 140) {
                    sgm16[(t*64 + h)*141 + s + 1]     = __float2bfloat16(acc[ni][1]);
                    sgm16[(t*64 + h + 8)*141 + s + 1] = __float2bfloat16(acc[ni][3]);
                }
            }
        }
        __syncthreads();                       // phiF ready

        // pass 1: scores for this frame (49 keys, 4 per group)
        #pragma unroll
        for (int g2 = 0; g2 < 13; g2++) {
            int q = g2*4 + sub;
            int qq = (q > 48) ? 48 : q;
            int dy = qq / 7, dx = qq - dy*7;
            int pos = warpPos + dy*14 + dx;
            uint4 pv = *(const uint4*)(ph16 + pos*72 + c*8);
            float2 p0 = __bfloat1622float2(*(__nv_bfloat162*)&pv.x);
            float2 p1 = __bfloat1622float2(*(__nv_bfloat162*)&pv.y);
            float2 p2 = __bfloat1622float2(*(__nv_bfloat162*)&pv.z);
            float2 p3 = __bfloat1622float2(*(__nv_bfloat162*)&pv.w);
            float s = qA.x*p0.x + qA.y*p0.y + qA.z*p1.x + qA.w*p1.y
                    + qB.x*p2.x + qB.y*p2.y + qB.z*p3.x + qB.w*p3.y;
            s += __shfl_xor_sync(0xffffffffu, s, 4);
            s += __shfl_xor_sync(0xffffffffu, s, 2);
            s += __shfl_xor_sync(0xffffffffu, s, 1);
            if (c == 0 && q <= 48) satt[warp*200 + t*49 + q] = s * 8.0f;
        }
    }
    __syncthreads();                           // last phiF reads done

    // ---- build packed scramble table offT into XU ----
    // flat index i = k*64 + j  ->  (h, t, dy, dx);  packed so one u64 load
    // fetches offsets for keys (2kk, 2kk+1) x channels (2l, 2l+1):
    //   dst[((kk*32 + l)<<2) + (kb<<1) + jb]
    {
        unsigned short* dst = (unsigned short*)(smc + XU_B);
        for (int i = tid; i < 12544; i += 1024) {
            int h  = i / 196;
            int r  = i - h*196;
            int t  = r / 49;
            int q  = r - t*49;
            int dy = q / 7;
            int dx = q - dy*7;
            int k  = i >> 6, j = i & 63;
            int idx = (((k >> 1)*32 + (j >> 1)) << 2) + ((k & 1) << 1) + (j & 1);
            dst[idx] = (unsigned short)((t*64 + h)*141 + dy*14 + dx);
        }
    }

    // ---- per-warp softmax; exp weights stored bf16 in-place ----
    float sv[7];
    float m = -1e30f;
    #pragma unroll
    for (int g2 = 0; g2 < 7; g2++) {
        int k = lane + 32*g2;
        sv[g2] = (k < 196) ? satt[warp*200 + k] : -1e30f;
        m = fmaxf(m, sv[g2]);
    }
    m = fmaxf(m, __shfl_xor_sync(0xffffffffu, m, 16));
    m = fmaxf(m, __shfl_xor_sync(0xffffffffu, m, 8));
    m = fmaxf(m, __shfl_xor_sync(0xffffffffu, m, 4));
    m = fmaxf(m, __shfl_xor_sync(0xffffffffu, m, 2));
    m = fmaxf(m, __shfl_xor_sync(0xffffffffu, m, 1));
    __syncwarp();
    float tot = 0.f;
    #pragma unroll
    for (int g2 = 0; g2 < 7; g2++) {
        int k = lane + 32*g2;
        if (k < 196) {
            float e = __expf(sv[g2] - m);
            satt16[warp*400 + k] = __float2bfloat16(e);
            tot += e;
        }
    }
    tot += __shfl_xor_sync(0xffffffffu, tot, 16);
    tot += __shfl_xor_sync(0xffffffffu, tot, 8);
    tot += __shfl_xor_sync(0xffffffffu, tot, 4);
    tot += __shfl_xor_sync(0xffffffffu, tot, 2);
    tot += __shfl_xor_sync(0xffffffffu, tot, 1);
    float inv = 1.0f / tot;

    __syncthreads();                           // offT ready

    // ---- pass 2: scrambled-V accumulation (channels 2*lane, 2*lane+1) ----
    const uint2* soff4 = (const uint2*)(smc + XU_B);   // 4 offsets per entry
    float acc0 = 0.f, acc1 = 0.f;
    for (int k = 0; k < 192; k += 8) {
        uint4 wv = *(const uint4*)(satt16 + warp*400 + k);
        float2 w0 = __bfloat1622float2(*(__nv_bfloat162*)&wv.x);
        float2 w1 = __bfloat1622float2(*(__nv_bfloat162*)&wv.y);
        float2 w2 = __bfloat1622float2(*(__nv_bfloat162*)&wv.z);
        float2 w3 = __bfloat1622float2(*(__nv_bfloat162*)&wv.w);
        float w8[8] = {w0.x, w0.y, w1.x, w1.y, w2.x, w2.y, w3.x, w3.y};
        #pragma unroll
        for (int u = 0; u < 8; u += 2) {
            uint2 ov = soff4[((k + u) >> 1)*32 + lane];
            ushort2 oA = *(ushort2*)&ov.x;     // key k+u
            ushort2 oB = *(ushort2*)&ov.y;     // key k+u+1
            acc0 = fmaf(w8[u],   __bfloat162float(sgm16[oA.x + warpPos]), acc0);
            acc1 = fmaf(w8[u],   __bfloat162float(sgm16[oA.y + warpPos]), acc1);
            acc0 = fmaf(w8[u+1], __bfloat162float(sgm16[oB.x + warpPos]), acc0);
            acc1 = fmaf(w8[u+1], __bfloat162float(sgm16[oB.y + warpPos]), acc1);
        }
    }
    {   // k = 192..195
        uint2 wv = *(const uint2*)(satt16 + warp*400 + 192);
        float2 w0 = __bfloat1622float2(*(__nv_bfloat162*)&wv.x);
        float2 w1 = __bfloat1622float2(*(__nv_bfloat162*)&wv.y);
        float w4[4] = {w0.x, w0.y, w1.x, w1.y};
        #pragma unroll
        for (int u = 0; u < 4; u += 2) {
            uint2 ov = soff4[((192 + u) >> 1)*32 + lane];
            ushort2 oA = *(ushort2*)&ov.x;
            ushort2 oB = *(ushort2*)&ov.y;
            acc0 = fmaf(w4[u],   __bfloat162float(sgm16[oA.x + warpPos]), acc0);
            acc1 = fmaf(w4[u],   __bfloat162float(sgm16[oA.y + warpPos]), acc1);
            acc0 = fmaf(w4[u+1], __bfloat162float(sgm16[oB.x + warpPos]), acc0);
            acc1 = fmaf(w4[u+1], __bfloat162float(sgm16[oB.y + warpPos]), acc1);
        }
    }
    float* yb = g_y + ((size_t)b*HW + p)*HCH;
    *(float2*)(yb + 2*lane) = make_float2(acc0*inv, acc1*inv);
}

// ---------------------------------------------------------------------------
// Kernel 2: output projection + residual (handles the y-reshape scramble).
// out[b,c,s] = x[b,c,0,s] + sum_h' w_out[c,h'] * y_flat[b][h'*2304 + s]
// grid (36,2,2), block 512, microtile 2c x 4s.  (best measured: 11.6us)
// ---------------------------------------------------------------------------
__global__ void out_kernel(const float* __restrict__ x,
                           const float* __restrict__ w_out,
                           float* __restrict__ out)
{
    __shared__ float sy [64*64];   // [h'][s]
    __shared__ float swt[64*68];   // [h'][c]
    const int s0  = blockIdx.x * 64;
    const int c0  = blockIdx.y * 64;
    const int b   = blockIdx.z;
    const int tid = threadIdx.x;
    const float* yb = g_y + (size_t)b*HW*HCH;
    for (int i = tid; i < 4096; i += 512) {
        int hh = i >> 6, s = i & 63;
        sy[i] = yb[hh*HW + s0 + s];
        int cc = i >> 6, h2 = i & 63;
        swt[h2*68 + cc] = w_out[(c0 + cc)*HCH + h2];
    }
    __syncthreads();
    const int sg2 = tid & 15;   // s = sg2*4 + i
    const int cg  = tid >> 4;   // c = cg*2 + j
    float acc[2][4] = {};
    #pragma unroll 4
    for (int hh = 0; hh < 64; hh++) {
        float4 yv = *(const float4*)(sy + hh*64 + sg2*4);
        float2 wv = *(const float2*)(swt + hh*68 + cg*2);
        float ys[4] = {yv.x, yv.y, yv.z, yv.w};
        float ws[2] = {wv.x, wv.y};
        #pragma unroll
        for (int j = 0; j < 2; j++)
            #pragma unroll
            for (int i = 0; i < 4; i++)
                acc[j][i] = fmaf(ws[j], ys[i], acc[j][i]);
    }
    #pragma unroll
    for (int j = 0; j < 2; j++) {
        int cc = c0 + cg*2 + j;
        float4 xv = *(const float4*)(x + ((size_t)(b*CIN + cc)*TT)*HW + s0 + sg2*4);
        float4 o  = make_float4(acc[j][0]+xv.x, acc[j][1]+xv.y,
                                acc[j][2]+xv.z, acc[j][3]+xv.w);
        *(float4*)(out + ((size_t)(b*CIN + cc))*HW + s0 + sg2*4) = o;
    }
}

extern "C" void kernel_launch(void* const* d_in, const int* in_sizes, int n_in,
                              void* d_out, int out_size)
{
    const float* x  = (const float*)d_in[0];
    const float* wt = (const float*)d_in[1];
    const float* wp = (const float*)d_in[2];
    const float* wg = (const float*)d_in[3];
    const float* wo = (const float*)d_in[4];
    float* out = (float*)d_out;

    cudaFuncSetAttribute(fused_attn_kernel,
                         cudaFuncAttributeMaxDynamicSharedMemorySize, SMEM_TOT);

    fused_attn_kernel<<<dim3(6, 12, 2), 1024, SMEM_TOT>>>(x, wt, wp, wg);
    out_kernel<<<dim3(36, 2, 2), 512>>>(x, wo, out);
}

// round 16
// speedup vs baseline: 1.5317x; 1.5317x over previous
#include <cuda_runtime.h>
#include <cuda_bf16.h>
#include <math.h>
#include <cstdint>

#define BATCH 2
#define CIN   128
#define TT    5
#define TC    4
#define HH    48
#define WW    48
#define HW    2304
#define HCH   64

// Scratch (device globals -- no allocation allowed)
__device__ float          g_q  [BATCH*HW*HCH];      // [b][p][h] fp32
__device__ float          g_phi[BATCH*TC*HW*HCH];   // [b][t][p][h] fp32
__device__ __nv_bfloat16  g_gb [BATCH*TC*HW*HCH];   // [b][t][p][h] bf16
__device__ float          g_y  [BATCH*HW*HCH];      // flat [b][p*64+j]

// ---------------------------------------------------------------------------
// Kernel 1: projections via warp-level bf16 HMMA (mma.sync m16n8k16).
// grid (36, 5, 2), block 256 (8 warps = 4m x 2n).   [R7, measured 21.1us]
// ---------------------------------------------------------------------------
#define WSTRIDE 68
#define XSTRIDE 72
#define PROJ_SMEM ((128*WSTRIDE + 64*XSTRIDE)*4)

__global__ void __launch_bounds__(256)
proj_kernel(const float* __restrict__ x,
            const float* __restrict__ w_theta,
            const float* __restrict__ w_phi,
            const float* __restrict__ w_g)
{
    extern __shared__ uint32_t smw[];              // W_sm [128][WSTRIDE]
    uint32_t* smx = smw + 128*WSTRIDE;             // X_sm [64][XSTRIDE]

    const int s0  = blockIdx.x * 64;
    const int f   = blockIdx.y;
    const int b   = blockIdx.z;
    const int tid = threadIdx.x;

    const float* wsrcA = (f == 0) ? w_theta : w_phi;
    const float* wsrcB = (f == 0) ? w_theta : w_g;
    for (int i = tid; i < 8192; i += 256) {
        int m = i >> 6, k2 = i & 63;
        const float* row = (m < 64) ? (wsrcA + m*CIN) : (wsrcB + (m - 64)*CIN);
        float2 wv = *(const float2*)(row + 2*k2);
        __nv_bfloat162 bp = __floats2bfloat162_rn(wv.x, wv.y);
        smw[m*WSTRIDE + k2] = *(uint32_t*)&bp;
    }
    const float* xb = x + ((size_t)(b*CIN))*TT*HW + (size_t)f*HW + s0;
    for (int i = tid; i < 4096; i += 256) {
        int k2 = i >> 6, n = i & 63;
        float x0 = xb[(size_t)(2*k2    )*(TT*HW) + n];
        float x1 = xb[(size_t)(2*k2 + 1)*(TT*HW) + n];
        __nv_bfloat162 bp = __floats2bfloat162_rn(x0, x1);
        smx[k2*XSTRIDE + n] = *(uint32_t*)&bp;
    }
    __syncthreads();

    const int warp = tid >> 5, lane = tid & 31;
    const int l4 = lane >> 2, lm4 = lane & 3;
    const int m0  = (warp & 3) * 32;
    const int n0w = (warp >> 2) * 32;

    if (f == 0 && m0 >= 64) return;   // duplicate theta rows; no syncthreads after

    float acc[2][4][4] = {};          // [mi][ni][c0..c3]
    #pragma unroll
    for (int k8 = 0; k8 < 8; k8++) {
        uint32_t a[2][4];
        #pragma unroll
        for (int mi = 0; mi < 2; mi++) {
            int r0 = m0 + mi*16 + l4;
            int cA = k8*8 + lm4;
            a[mi][0] = smw[r0*WSTRIDE + cA];
            a[mi][1] = smw[(r0 + 8)*WSTRIDE + cA];
            a[mi][2] = smw[r0*WSTRIDE + cA + 4];
            a[mi][3] = smw[(r0 + 8)*WSTRIDE + cA + 4];
        }
        #pragma unroll
        for (int ni = 0; ni < 4; ni++) {
            int ncol = n0w + ni*8 + l4;
            uint32_t b0 = smx[(k8*8 + lm4    )*XSTRIDE + ncol];
            uint32_t b1 = smx[(k8*8 + lm4 + 4)*XSTRIDE + ncol];
            #pragma unroll
            for (int mi = 0; mi < 2; mi++) {
                asm volatile(
                    "mma.sync.aligned.m16n8k16.row.col.f32.bf16.bf16.f32 "
                    "{%0,%1,%2,%3}, {%4,%5,%6,%7}, {%8,%9}, {%0,%1,%2,%3};\n"
                    : "+f"(acc[mi][ni][0]), "+f"(acc[mi][ni][1]),
                      "+f"(acc[mi][ni][2]), "+f"(acc[mi][ni][3])
                    : "r"(a[mi][0]), "r"(a[mi][1]), "r"(a[mi][2]), "r"(a[mi][3]),
                      "r"(b0), "r"(b1));
            }
        }
    }

    const int t = f - 1;
    #pragma unroll
    for (int mi = 0; mi < 2; mi++) {
        int r = m0 + mi*16 + l4;
        #pragma unroll
        for (int ni = 0; ni < 4; ni++) {
            int s = s0 + n0w + ni*8 + lm4*2;
            if (f == 0) {
                float* q = g_q + (size_t)b*HW*HCH;
                q[(size_t)(s    )*HCH + r]     = acc[mi][ni][0];
                q[(size_t)(s + 1)*HCH + r]     = acc[mi][ni][1];
                q[(size_t)(s    )*HCH + r + 8] = acc[mi][ni][2];
                q[(size_t)(s + 1)*HCH + r + 8] = acc[mi][ni][3];
            } else if (m0 < 64) {
                float* ph = g_phi + ((size_t)(b*TC + t)*HW)*HCH;
                ph[(size_t)(s    )*HCH + r]     = acc[mi][ni][0];
                ph[(size_t)(s + 1)*HCH + r]     = acc[mi][ni][1];
                ph[(size_t)(s    )*HCH + r + 8] = acc[mi][ni][2];
                ph[(size_t)(s + 1)*HCH + r + 8] = acc[mi][ni][3];
            } else {
                __nv_bfloat16* gg = g_gb + ((size_t)(b*TC + t)*HW)*HCH;
                int h = r - 64;
                gg[(size_t)(s    )*HCH + h]     = __float2bfloat16(acc[mi][ni][0]);
                gg[(size_t)(s + 1)*HCH + h]     = __float2bfloat16(acc[mi][ni][1]);
                gg[(size_t)(s    )*HCH + h + 8] = __float2bfloat16(acc[mi][ni][2]);
                gg[(size_t)(s + 1)*HCH + h + 8] = __float2bfloat16(acc[mi][ni][3]);
            }
        }
    }
}

// ---------------------------------------------------------------------------
// Kernel 2: attention, 2 CTAs/SM.  grid (12,12,2) = 288 blocks, 512 thr
// (16 warps = 4x4 pixel tile), halo 10x10 = 100 positions.
// Smem layout (bytes), total 92112 -> 2 CTAs resident:
//   [0, 51712)          sgm16: g halos bf16 [t][64 ch][101 pos]
//   [51712, 78912)      UNION: phi fp32 [100][68] (pass1) / offT u16[12544]
//   [78912, 91712)      satt fp32 [16 warps][200]
//   [91712, 92112)      sgp int[100]
// ---------------------------------------------------------------------------
#define SGM_B   0
#define UNI_B   51712
#define SATT_B  78912
#define SGP_B   91712
#define SMEM_B  92112

__global__ void __launch_bounds__(512, 2) attn_kernel()
{
    extern __shared__ char smc[];
    __nv_bfloat16* sgm16 = (__nv_bfloat16*)(smc + SGM_B);
    float*         sphi  = (float*)(smc + UNI_B);
    float*         satt  = (float*)(smc + SATT_B);
    int*           sgp   = (int*)(smc + SGP_B);

    const int b    = blockIdx.z;
    const int tid  = threadIdx.x;
    const int lane = tid & 31, warp = tid >> 5;
    const int ly = warp >> 2, lx = warp & 3;       // 4x4 tile
    const int py = blockIdx.y*4 + ly;
    const int px = blockIdx.x*4 + lx;
    const int p  = py*WW + px;
    const int warpPos = ly*10 + lx;

    if (tid < 100) {
        int hy = tid / 10, hx = tid - hy*10;
        int gy = min(max((int)blockIdx.y*4 + hy - 3, 0), HH-1);
        int gx = min(max((int)blockIdx.x*4 + hx - 3, 0), WW-1);
        sgp[tid] = (gy*WW + gx)*HCH;
    }
    __syncthreads();

    // ---- stage all 4 frames of g halos, bf16 channel-major [t][h][101] ----
    const __nv_bfloat16* gBase = g_gb + (size_t)b*TC*HW*HCH;
    for (int i = tid; i < 400*32; i += 512) {
        int h2  = i & 31;          // channel pair 2h2, 2h2+1
        int pr  = i >> 5;
        int pos = pr % 100;
        int t   = pr / 100;
        unsigned int v = *(const unsigned int*)(gBase + (size_t)t*HW*HCH + sgp[pos] + 2*h2);
        __nv_bfloat162 bv = *(__nv_bfloat162*)&v;
        sgm16[(t*64 + 2*h2    )*101 + pos] = bv.x;
        sgm16[(t*64 + 2*h2 + 1)*101 + pos] = bv.y;
    }

    // ---- q for this pixel ----
    const float* qb = g_q + ((size_t)b*HW + p)*HCH;
    const int c   = lane & 7;    // channel chunk within key group
    const int sub = lane >> 3;   // key within group of 4
    float4 qv0 = *(const float4*)(qb + c*4);
    float4 qv1 = *(const float4*)(qb + c*4 + 32);
    float  q0r = qb[lane], q1r = qb[lane + 32];

    // ---- pass 1: scores (phi fp32, unscrambled) ----
    const float* pBase = g_phi + (size_t)b*TC*HW*HCH;
    for (int t = 0; t < TC; t++) {
        __syncthreads();
        for (int i = tid; i < 100*16; i += 512) {
            int c4 = i & 15, pos = i >> 4;
            *(float4*)(sphi + pos*68 + c4*4) =
                *(const float4*)(pBase + (size_t)t*HW*HCH + sgp[pos] + c4*4);
        }
        __syncthreads();

        #pragma unroll
        for (int g2 = 0; g2 < 12; g2++) {
            int q  = g2*4 + sub;
            int dy = q / 7, dx = q - dy*7;
            int pos = warpPos + dy*10 + dx;
            const float4* pr4 = (const float4*)(sphi + pos*68);
            float4 p0 = pr4[c];
            float4 p1 = pr4[8 + c];
            float s = qv0.x*p0.x + qv0.y*p0.y + qv0.z*p0.z + qv0.w*p0.w
                    + qv1.x*p1.x + qv1.y*p1.y + qv1.z*p1.z + qv1.w*p1.w;
            s += __shfl_xor_sync(0xffffffffu, s, 4);
            s += __shfl_xor_sync(0xffffffffu, s, 2);
            s += __shfl_xor_sync(0xffffffffu, s, 1);
            if (c == 0) satt[warp*200 + t*49 + q] = s * 8.0f;
        }
        {   // leftover key q=48 (dy=6, dx=6)
            int pos = warpPos + 66;
            float s = q0r*sphi[pos*68 + lane] + q1r*sphi[pos*68 + lane + 32];
            s += __shfl_xor_sync(0xffffffffu, s, 16);
            s += __shfl_xor_sync(0xffffffffu, s, 8);
            s += __shfl_xor_sync(0xffffffffu, s, 4);
            s += __shfl_xor_sync(0xffffffffu, s, 2);
            s += __shfl_xor_sync(0xffffffffu, s, 1);
            if (lane == 0) satt[warp*200 + t*49 + 48] = s * 8.0f;
        }
    }
    __syncthreads();   // pass-1 phi reads done; union region free

    // ---- compute scramble table (ushort) into union region ----
    {
        unsigned short* dst = (unsigned short*)(smc + UNI_B);
        for (int i = tid; i < 12544; i += 512) {
            int h  = i / 196;
            int r  = i - h*196;
            int t  = r / 49;
            int q  = r - t*49;
            int dy = q / 7;
            int dx = q - dy*7;
            dst[i] = (unsigned short)((t*64 + h)*101 + dy*10 + dx);
        }
    }

    // ---- per-warp softmax (deferred normalization) ----
    float sv[7];
    float m = -1e30f;
    #pragma unroll
    for (int g2 = 0; g2 < 7; g2++) {
        int k = lane + 32*g2;
        sv[g2] = (k < 196) ? satt[warp*200 + k] : -1e30f;
        m = fmaxf(m, sv[g2]);
    }
    m = fmaxf(m, __shfl_xor_sync(0xffffffffu, m, 16));
    m = fmaxf(m, __shfl_xor_sync(0xffffffffu, m, 8));
    m = fmaxf(m, __shfl_xor_sync(0xffffffffu, m, 4));
    m = fmaxf(m, __shfl_xor_sync(0xffffffffu, m, 2));
    m = fmaxf(m, __shfl_xor_sync(0xffffffffu, m, 1));
    float tot = 0.f;
    #pragma unroll
    for (int g2 = 0; g2 < 7; g2++) {
        int k = lane + 32*g2;
        if (k < 196) {
            float e = __expf(sv[g2] - m);
            satt[warp*200 + k] = e;
            tot += e;
        }
    }
    tot += __shfl_xor_sync(0xffffffffu, tot, 16);
    tot += __shfl_xor_sync(0xffffffffu, tot, 8);
    tot += __shfl_xor_sync(0xffffffffu, tot, 4);
    tot += __shfl_xor_sync(0xffffffffu, tot, 2);
    tot += __shfl_xor_sync(0xffffffffu, tot, 1);
    float inv = 1.0f / tot;

    __syncthreads();   // offT ready

    // ---- pass 2: scrambled-V accumulation (channels 2*lane, 2*lane+1) ----
    const ushort2* soff2 = (const ushort2*)(smc + UNI_B);
    float acc0 = 0.f, acc1 = 0.f;
    for (int k = 0; k < 196; k += 4) {
        float4 w4 = *(const float4*)(satt + warp*200 + k);
        float wv[4] = {w4.x, w4.y, w4.z, w4.w};
        #pragma unroll
        for (int u = 0; u < 4; u++) {
            ushort2 o = soff2[(k + u)*32 + lane];
            acc0 = fmaf(wv[u], __bfloat162float(sgm16[o.x + warpPos]), acc0);
            acc1 = fmaf(wv[u], __bfloat162float(sgm16[o.y + warpPos]), acc1);
        }
    }
    float* yb = g_y + ((size_t)b*HW + p)*HCH;
    *(float2*)(yb + 2*lane) = make_float2(acc0*inv, acc1*inv);
}

// ---------------------------------------------------------------------------
// Kernel 3: output projection + residual (handles the y-reshape scramble).
// out[b,c,s] = x[b,c,0,s] + sum_h' w_out[c,h'] * y_flat[b][h'*2304 + s]
// grid (36,2,2), block 512, microtile 2c x 4s.  [R7, best measured]
// ---------------------------------------------------------------------------
__global__ void out_kernel(const float* __restrict__ x,
                           const float* __restrict__ w_out,
                           float* __restrict__ out)
{
    __shared__ float sy [64*64];   // [h'][s]
    __shared__ float swt[64*68];   // [h'][c]
    const int s0  = blockIdx.x * 64;
    const int c0  = blockIdx.y * 64;
    const int b   = blockIdx.z;
    const int tid = threadIdx.x;
    const float* yb = g_y + (size_t)b*HW*HCH;
    for (int i = tid; i < 4096; i += 512) {
        int hh = i >> 6, s = i & 63;
        sy[i] = yb[hh*HW + s0 + s];
        int cc = i >> 6, h2 = i & 63;
        swt[h2*68 + cc] = w_out[(c0 + cc)*HCH + h2];
    }
    __syncthreads();
    const int sg2 = tid & 15;   // s = sg2*4 + i
    const int cg  = tid >> 4;   // c = cg*2 + j
    float acc[2][4] = {};
    #pragma unroll 4
    for (int hh = 0; hh < 64; hh++) {
        float4 yv = *(const float4*)(sy + hh*64 + sg2*4);
        float2 wv = *(const float2*)(swt + hh*68 + cg*2);
        float ys[4] = {yv.x, yv.y, yv.z, yv.w};
        float ws[2] = {wv.x, wv.y};
        #pragma unroll
        for (int j = 0; j < 2; j++)
            #pragma unroll
            for (int i = 0; i < 4; i++)
                acc[j][i] = fmaf(ws[j], ys[i], acc[j][i]);
    }
    #pragma unroll
    for (int j = 0; j < 2; j++) {
        int cc = c0 + cg*2 + j;
        float4 xv = *(const float4*)(x + ((size_t)(b*CIN + cc)*TT)*HW + s0 + sg2*4);
        float4 o  = make_float4(acc[j][0]+xv.x, acc[j][1]+xv.y,
                                acc[j][2]+xv.z, acc[j][3]+xv.w);
        *(float4*)(out + ((size_t)(b*CIN + cc))*HW + s0 + sg2*4) = o;
    }
}

extern "C" void kernel_launch(void* const* d_in, const int* in_sizes, int n_in,
                              void* d_out, int out_size)
{
    const float* x  = (const float*)d_in[0];
    const float* wt = (const float*)d_in[1];
    const float* wp = (const float*)d_in[2];
    const float* wg = (const float*)d_in[3];
    const float* wo = (const float*)d_in[4];
    float* out = (float*)d_out;

    cudaFuncSetAttribute(proj_kernel, cudaFuncAttributeMaxDynamicSharedMemorySize, PROJ_SMEM);
    cudaFuncSetAttribute(attn_kernel, cudaFuncAttributeMaxDynamicSharedMemorySize, SMEM_B);

    proj_kernel<<<dim3(36, 5, 2), 256, PROJ_SMEM>>>(x, wt, wp, wg);
    attn_kernel<<<dim3(12, 12, 2), 512, SMEM_B>>>();
    out_kernel<<<dim3(36, 2, 2), 512>>>(x, wo, out);
}

// round 17
// speedup vs baseline: 1.6255x; 1.0612x over previous
#include <cuda_runtime.h>
#include <cuda_bf16.h>
#include <math.h>
#include <cstdint>

#define BATCH 2
#define CIN   128
#define TT    5
#define TC    4
#define HH    48
#define WW    48
#define HW    2304
#define HCH   64

// Scratch (device globals -- no allocation allowed)
__device__ float          g_q  [BATCH*HW*HCH];      // [b][p][h] fp32
__device__ float          g_phi[BATCH*TC*HW*HCH];   // [b][t][p][h] fp32
__device__ __nv_bfloat16  g_gb [BATCH*TC*HW*HCH];   // [b][t][p][h] bf16
__device__ float          g_y  [BATCH*HW*HCH];      // flat [b][p*64+j]

// ---------------------------------------------------------------------------
// Kernel 1: projections via warp-level bf16 HMMA, smem-transposed epilogue.
// grid (36, 5, 2), block 256 (8 warps = 4m x 2n).
// D[128 out][64 px] = A[128,128] x B[128,64]; A = [phi; g] ([theta; dup] f=0).
// smem: W_sm u32[128][68], X_sm u32[64][72];
// epilogue aliases: smT f32[64 s][68] (phi/q) over X_sm, smT2 bf16[64 s][72]
// (g) over W_sm -> coalesced STG.128 / u32 writes.
// ---------------------------------------------------------------------------
#define WSTRIDE 68
#define XSTRIDE 72
#define PROJ_SMEM ((128*WSTRIDE + 64*XSTRIDE)*4)

__global__ void __launch_bounds__(256)
proj_kernel(const float* __restrict__ x,
            const float* __restrict__ w_theta,
            const float* __restrict__ w_phi,
            const float* __restrict__ w_g)
{
    extern __shared__ uint32_t smw[];              // W_sm [128][WSTRIDE]
    uint32_t* smx = smw + 128*WSTRIDE;             // X_sm [64][XSTRIDE]

    const int s0  = blockIdx.x * 64;
    const int f   = blockIdx.y;
    const int b   = blockIdx.z;
    const int tid = threadIdx.x;

    const float* wsrcA = (f == 0) ? w_theta : w_phi;
    const float* wsrcB = (f == 0) ? w_theta : w_g;
    for (int i = tid; i < 8192; i += 256) {
        int m = i >> 6, k2 = i & 63;
        const float* row = (m < 64) ? (wsrcA + m*CIN) : (wsrcB + (m - 64)*CIN);
        float2 wv = *(const float2*)(row + 2*k2);
        __nv_bfloat162 bp = __floats2bfloat162_rn(wv.x, wv.y);
        smw[m*WSTRIDE + k2] = *(uint32_t*)&bp;
    }
    const float* xb = x + ((size_t)(b*CIN))*TT*HW + (size_t)f*HW + s0;
    for (int i = tid; i < 4096; i += 256) {
        int k2 = i >> 6, n = i & 63;
        float x0 = xb[(size_t)(2*k2    )*(TT*HW) + n];
        float x1 = xb[(size_t)(2*k2 + 1)*(TT*HW) + n];
        __nv_bfloat162 bp = __floats2bfloat162_rn(x0, x1);
        smx[k2*XSTRIDE + n] = *(uint32_t*)&bp;
    }
    __syncthreads();

    const int warp = tid >> 5, lane = tid & 31;
    const int l4 = lane >> 2, lm4 = lane & 3;
    const int m0  = (warp & 3) * 32;
    const int n0w = (warp >> 2) * 32;

    float acc[2][4][4] = {};          // [mi][ni][c0..c3]
    #pragma unroll
    for (int k8 = 0; k8 < 8; k8++) {
        uint32_t a[2][4];
        #pragma unroll
        for (int mi = 0; mi < 2; mi++) {
            int r0 = m0 + mi*16 + l4;
            int cA = k8*8 + lm4;
            a[mi][0] = smw[r0*WSTRIDE + cA];
            a[mi][1] = smw[(r0 + 8)*WSTRIDE + cA];
            a[mi][2] = smw[r0*WSTRIDE + cA + 4];
            a[mi][3] = smw[(r0 + 8)*WSTRIDE + cA + 4];
        }
        #pragma unroll
        for (int ni = 0; ni < 4; ni++) {
            int ncol = n0w + ni*8 + l4;
            uint32_t b0 = smx[(k8*8 + lm4    )*XSTRIDE + ncol];
            uint32_t b1 = smx[(k8*8 + lm4 + 4)*XSTRIDE + ncol];
            #pragma unroll
            for (int mi = 0; mi < 2; mi++) {
                asm volatile(
                    "mma.sync.aligned.m16n8k16.row.col.f32.bf16.bf16.f32 "
                    "{%0,%1,%2,%3}, {%4,%5,%6,%7}, {%8,%9}, {%0,%1,%2,%3};\n"
                    : "+f"(acc[mi][ni][0]), "+f"(acc[mi][ni][1]),
                      "+f"(acc[mi][ni][2]), "+f"(acc[mi][ni][3])
                    : "r"(a[mi][0]), "r"(a[mi][1]), "r"(a[mi][2]), "r"(a[mi][3]),
                      "r"(b0), "r"(b1));
            }
        }
    }
    __syncthreads();   // all smw/smx reads done -> alias regions

    float*         smT  = (float*)smx;             // [64 s][68] phi or q
    __nv_bfloat16* smT2 = (__nv_bfloat16*)smw;     // [64 s][72] g

    if (m0 < 64) {
        #pragma unroll
        for (int mi = 0; mi < 2; mi++) {
            int r = m0 + mi*16 + l4;
            #pragma unroll
            for (int ni = 0; ni < 4; ni++) {
                int s = n0w + ni*8 + lm4*2;
                smT[s*68 + r]           = acc[mi][ni][0];
                smT[(s + 1)*68 + r]     = acc[mi][ni][1];
                smT[s*68 + r + 8]       = acc[mi][ni][2];
                smT[(s + 1)*68 + r + 8] = acc[mi][ni][3];
            }
        }
    } else if (f > 0) {
        #pragma unroll
        for (int mi = 0; mi < 2; mi++) {
            int h = m0 - 64 + mi*16 + l4;
            #pragma unroll
            for (int ni = 0; ni < 4; ni++) {
                int s = n0w + ni*8 + lm4*2;
                smT2[s*72 + h]           = __float2bfloat16(acc[mi][ni][0]);
                smT2[(s + 1)*72 + h]     = __float2bfloat16(acc[mi][ni][1]);
                smT2[s*72 + h + 8]       = __float2bfloat16(acc[mi][ni][2]);
                smT2[(s + 1)*72 + h + 8] = __float2bfloat16(acc[mi][ni][3]);
            }
        }
    }
    __syncthreads();

    // ---- coalesced writeout ----
    if (f == 0) {
        float* qdst = g_q + ((size_t)b*HW + s0)*HCH;
        for (int i = tid; i < 1024; i += 256) {
            int s = i >> 4, c4 = i & 15;
            *(float4*)(qdst + (size_t)s*HCH + c4*4) = *(const float4*)(smT + s*68 + c4*4);
        }
    } else {
        const int t = f - 1;
        float* pdst = g_phi + ((size_t)(b*TC + t)*HW + s0)*HCH;
        for (int i = tid; i < 1024; i += 256) {
            int s = i >> 4, c4 = i & 15;
            *(float4*)(pdst + (size_t)s*HCH + c4*4) = *(const float4*)(smT + s*68 + c4*4);
        }
        uint32_t* gdst = (uint32_t*)(g_gb + ((size_t)(b*TC + t)*HW + s0)*HCH);
        const uint32_t* gsrc = (const uint32_t*)smT2;
        for (int i = tid; i < 2048; i += 256) {
            int s = i >> 5, cp = i & 31;
            gdst[s*32 + cp] = gsrc[s*36 + cp];
        }
    }
}

// ---------------------------------------------------------------------------
// Kernel 2: attention.  [R7 verbatim, best measured]
// grid (6,12,2), block 1024 (32 warps = 4x8 pixel tile).
// ---------------------------------------------------------------------------
#define SGM_B   0
#define UNI_B   72192
#define SATT_B  110272
#define SGP_B   135872
#define SMEM_B  136432

__global__ void attn_kernel()
{
    extern __shared__ char smc[];
    __nv_bfloat16* sgm16 = (__nv_bfloat16*)(smc + SGM_B);
    float*         sphi  = (float*)(smc + UNI_B);
    float*         satt  = (float*)(smc + SATT_B);
    int*           sgp   = (int*)(smc + SGP_B);

    const int b    = blockIdx.z;
    const int tid  = threadIdx.x;
    const int lane = tid & 31, warp = tid >> 5;
    const int ly = warp >> 3, lx = warp & 7;
    const int py = blockIdx.y*4 + ly;
    const int px = blockIdx.x*8 + lx;
    const int p  = py*WW + px;
    const int warpPos = ly*14 + lx;

    if (tid < 140) {
        int hy = tid / 14, hx = tid - hy*14;
        int gy = min(max((int)blockIdx.y*4 + hy - 3, 0), HH-1);
        int gx = min(max((int)blockIdx.x*8 + hx - 3, 0), WW-1);
        sgp[tid] = (gy*WW + gx)*HCH;
    }
    __syncthreads();

    // ---- stage all 4 frames of g halos, bf16 channel-major [t][h][141] ----
    const __nv_bfloat16* gBase = g_gb + (size_t)b*TC*HW*HCH;
    for (int i = tid; i < 560*32; i += 1024) {
        int h2  = i & 31;
        int pr  = i >> 5;
        int pos = pr % 140;
        int t   = pr / 140;
        unsigned int v = *(const unsigned int*)(gBase + (size_t)t*HW*HCH + sgp[pos] + 2*h2);
        __nv_bfloat162 bv = *(__nv_bfloat162*)&v;
        sgm16[(t*64 + 2*h2    )*141 + pos] = bv.x;
        sgm16[(t*64 + 2*h2 + 1)*141 + pos] = bv.y;
    }

    // ---- q for this pixel ----
    const float* qb = g_q + ((size_t)b*HW + p)*HCH;
    const int c   = lane & 7;
    const int sub = lane >> 3;
    float4 qv0 = *(const float4*)(qb + c*4);
    float4 qv1 = *(const float4*)(qb + c*4 + 32);
    float  q0r = qb[lane], q1r = qb[lane + 32];

    // ---- pass 1: scores (phi fp32, unscrambled) ----
    const float* pBase = g_phi + (size_t)b*TC*HW*HCH;
    for (int t = 0; t < TC; t++) {
        __syncthreads();
        for (int i = tid; i < 140*16; i += 1024) {
            int c4 = i & 15, pos = i >> 4;
            *(float4*)(sphi + pos*68 + c4*4) =
                *(const float4*)(pBase + (size_t)t*HW*HCH + sgp[pos] + c4*4);
        }
        __syncthreads();

        #pragma unroll
        for (int g2 = 0; g2 < 12; g2++) {
            int q  = g2*4 + sub;
            int dy = q / 7, dx = q - dy*7;
            int pos = warpPos + dy*14 + dx;
            const float4* pr4 = (const float4*)(sphi + pos*68);
            float4 p0 = pr4[c];
            float4 p1 = pr4[8 + c];
            float s = qv0.x*p0.x + qv0.y*p0.y + qv0.z*p0.z + qv0.w*p0.w
                    + qv1.x*p1.x + qv1.y*p1.y + qv1.z*p1.z + qv1.w*p1.w;
            s += __shfl_xor_sync(0xffffffffu, s, 4);
            s += __shfl_xor_sync(0xffffffffu, s, 2);
            s += __shfl_xor_sync(0xffffffffu, s, 1);
            if (c == 0) satt[warp*200 + t*49 + q] = s * 8.0f;
        }
        {   // leftover key q=48
            int pos = warpPos + 90;
            float s = q0r*sphi[pos*68 + lane] + q1r*sphi[pos*68 + lane + 32];
            s += __shfl_xor_sync(0xffffffffu, s, 16);
            s += __shfl_xor_sync(0xffffffffu, s, 8);
            s += __shfl_xor_sync(0xffffffffu, s, 4);
            s += __shfl_xor_sync(0xffffffffu, s, 2);
            s += __shfl_xor_sync(0xffffffffu, s, 1);
            if (lane == 0) satt[warp*200 + t*49 + 48] = s * 8.0f;
        }
    }
    __syncthreads();

    // ---- compute scramble table (ushort) into union region ----
    {
        unsigned short* dst = (unsigned short*)(smc + UNI_B);
        for (int i = tid; i < 12544; i += 1024) {
            int h  = i / 196;
            int r  = i - h*196;
            int t  = r / 49;
            int q  = r - t*49;
            int dy = q / 7;
            int dx = q - dy*7;
            dst[i] = (unsigned short)((t*64 + h)*141 + dy*14 + dx);
        }
    }

    // ---- per-warp softmax (deferred normalization) ----
    float sv[7];
    float m = -1e30f;
    #pragma unroll
    for (int g2 = 0; g2 < 7; g2++) {
        int k = lane + 32*g2;
        sv[g2] = (k < 196) ? satt[warp*200 + k] : -1e30f;
        m = fmaxf(m, sv[g2]);
    }
    m = fmaxf(m, __shfl_xor_sync(0xffffffffu, m, 16));
    m = fmaxf(m, __shfl_xor_sync(0xffffffffu, m, 8));
    m = fmaxf(m, __shfl_xor_sync(0xffffffffu, m, 4));
    m = fmaxf(m, __shfl_xor_sync(0xffffffffu, m, 2));
    m = fmaxf(m, __shfl_xor_sync(0xffffffffu, m, 1));
    float tot = 0.f;
    #pragma unroll
    for (int g2 = 0; g2 < 7; g2++) {
        int k = lane + 32*g2;
        if (k < 196) {
            float e = __expf(sv[g2] - m);
            satt[warp*200 + k] = e;
            tot += e;
        }
    }
    tot += __shfl_xor_sync(0xffffffffu, tot, 16);
    tot += __shfl_xor_sync(0xffffffffu, tot, 8);
    tot += __shfl_xor_sync(0xffffffffu, tot, 4);
    tot += __shfl_xor_sync(0xffffffffu, tot, 2);
    tot += __shfl_xor_sync(0xffffffffu, tot, 1);
    float inv = 1.0f / tot;

    __syncthreads();   // offT ready

    // ---- pass 2: scrambled-V accumulation ----
    const ushort2* soff2 = (const ushort2*)(smc + UNI_B);
    float acc0 = 0.f, acc1 = 0.f;
    for (int k = 0; k < 196; k += 4) {
        float4 w4 = *(const float4*)(satt + warp*200 + k);
        float wv[4] = {w4.x, w4.y, w4.z, w4.w};
        #pragma unroll
        for (int u = 0; u < 4; u++) {
            ushort2 o = soff2[(k + u)*32 + lane];
            acc0 = fmaf(wv[u], __bfloat162float(sgm16[o.x + warpPos]), acc0);
            acc1 = fmaf(wv[u], __bfloat162float(sgm16[o.y + warpPos]), acc1);
        }
    }
    float* yb = g_y + ((size_t)b*HW + p)*HCH;
    *(float2*)(yb + 2*lane) = make_float2(acc0*inv, acc1*inv);
}

// ---------------------------------------------------------------------------
// Kernel 3: output projection + residual.  [R7 verbatim]
// grid (36,2,2), block 512, microtile 2c x 4s.
// ---------------------------------------------------------------------------
__global__ void out_kernel(const float* __restrict__ x,
                           const float* __restrict__ w_out,
                           float* __restrict__ out)
{
    __shared__ float sy [64*64];
    __shared__ float swt[64*68];
    const int s0  = blockIdx.x * 64;
    const int c0  = blockIdx.y * 64;
    const int b   = blockIdx.z;
    const int tid = threadIdx.x;
    const float* yb = g_y + (size_t)b*HW*HCH;
    for (int i = tid; i < 4096; i += 512) {
        int hh = i >> 6, s = i & 63;
        sy[i] = yb[hh*HW + s0 + s];
        int cc = i >> 6, h2 = i & 63;
        swt[h2*68 + cc] = w_out[(c0 + cc)*HCH + h2];
    }
    __syncthreads();
    const int sg2 = tid & 15;
    const int cg  = tid >> 4;
    float acc[2][4] = {};
    #pragma unroll 4
    for (int hh = 0; hh < 64; hh++) {
        float4 yv = *(const float4*)(sy + hh*64 + sg2*4);
        float2 wv = *(const float2*)(swt + hh*68 + cg*2);
        float ys[4] = {yv.x, yv.y, yv.z, yv.w};
        float ws[2] = {wv.x, wv.y};
        #pragma unroll
        for (int j = 0; j < 2; j++)
            #pragma unroll
            for (int i = 0; i < 4; i++)
                acc[j][i] = fmaf(ws[j], ys[i], acc[j][i]);
    }
    #pragma unroll
    for (int j = 0; j < 2; j++) {
        int cc = c0 + cg*2 + j;
        float4 xv = *(const float4*)(x + ((size_t)(b*CIN + cc)*TT)*HW + s0 + sg2*4);
        float4 o  = make_float4(acc[j][0]+xv.x, acc[j][1]+xv.y,
                                acc[j][2]+xv.z, acc[j][3]+xv.w);
        *(float4*)(out + ((size_t)(b*CIN + cc))*HW + s0 + sg2*4) = o;
    }
}

extern "C" void kernel_launch(void* const* d_in, const int* in_sizes, int n_in,
                              void* d_out, int out_size)
{
    const float* x  = (const float*)d_in[0];
    const float* wt = (const float*)d_in[1];
    const float* wp = (const float*)d_in[2];
    const float* wg = (const float*)d_in[3];
    const float* wo = (const float*)d_in[4];
    float* out = (float*)d_out;

    cudaFuncSetAttribute(proj_kernel, cudaFuncAttributeMaxDynamicSharedMemorySize, PROJ_SMEM);
    cudaFuncSetAttribute(attn_kernel, cudaFuncAttributeMaxDynamicSharedMemorySize, SMEM_B);

    proj_kernel<<<dim3(36, 5, 2), 256, PROJ_SMEM>>>(x, wt, wp, wg);
    attn_kernel<<<dim3(6, 12, 2), 1024, SMEM_B>>>();
    out_kernel<<<dim3(36, 2, 2), 512>>>(x, wo, out);
}